// round 1
// baseline (speedup 1.0000x reference)
#include <cuda_runtime.h>
#include <math.h>

#define BSZ 2
#define SEQ 2048
#define DIM 4096
#define NH 32
#define NKV 8
#define HD 128

// Scratch (static device globals — no allocation allowed in kernel_launch)
__device__ float g_q[BSZ*SEQ*NH*HD];    // 64 MB
__device__ float g_k[BSZ*SEQ*NKV*HD];   // 16 MB
__device__ float g_v[BSZ*SEQ*NKV*HD];   // 16 MB
__device__ float g_o[BSZ*SEQ*NH*HD];    // 64 MB

// ---------------------------------------------------------------------------
// SGEMM: C[M,N] = A[M,K] * B[K,N], all row-major fp32.
// 128x128 block tile, BK=16, 256 threads, 8x8 micro-tile per thread.
// ---------------------------------------------------------------------------
__global__ __launch_bounds__(256) void sgemm_kernel(
    const float* __restrict__ A, const float* __restrict__ B,
    float* __restrict__ C, int M, int N, int K)
{
    __shared__ float As[16][132];   // stored transposed: As[k][m]
    __shared__ float Bs[16][132];   // Bs[k][n]

    const int t  = threadIdx.x;
    const int m0 = blockIdx.y * 128;
    const int n0 = blockIdx.x * 128;
    const int tx = t & 15;          // n direction
    const int ty = t >> 4;          // m direction

    // load indices
    const int arow = t >> 2;        // 0..63 (two passes +64)
    const int akq  = t & 3;         // float4 group in K
    const int bk   = t >> 5;        // 0..7  (two passes +8)
    const int bn4  = t & 31;        // float4 col

    float acc[8][8];
#pragma unroll
    for (int i = 0; i < 8; i++)
#pragma unroll
        for (int j = 0; j < 8; j++) acc[i][j] = 0.f;

    for (int k0 = 0; k0 < K; k0 += 16) {
#pragma unroll
        for (int r = 0; r < 2; r++) {
            int row = arow + r * 64;
            float4 v = *(const float4*)(A + (size_t)(m0 + row) * K + k0 + akq * 4);
            As[akq*4+0][row] = v.x;
            As[akq*4+1][row] = v.y;
            As[akq*4+2][row] = v.z;
            As[akq*4+3][row] = v.w;
        }
#pragma unroll
        for (int r = 0; r < 2; r++) {
            int kk = bk + r * 8;
            *(float4*)(&Bs[kk][bn4*4]) =
                *(const float4*)(B + (size_t)(k0 + kk) * N + n0 + bn4 * 4);
        }
        __syncthreads();

#pragma unroll
        for (int kk = 0; kk < 16; kk++) {
            float a[8], b[8];
#pragma unroll
            for (int i = 0; i < 8; i++) a[i] = As[kk][ty*8 + i];
#pragma unroll
            for (int j = 0; j < 8; j++) b[j] = Bs[kk][tx + 16*j];
#pragma unroll
            for (int i = 0; i < 8; i++)
#pragma unroll
                for (int j = 0; j < 8; j++) acc[i][j] += a[i] * b[j];
        }
        __syncthreads();
    }

#pragma unroll
    for (int i = 0; i < 8; i++) {
        size_t rowoff = (size_t)(m0 + ty*8 + i) * N + n0;
#pragma unroll
        for (int j = 0; j < 8; j++)
            C[rowoff + tx + 16*j] = acc[i][j];
    }
}

// ---------------------------------------------------------------------------
// RoPE (in place). Pair index layout: ((b*SEQ+s)*nh + h)*64 + p
// ---------------------------------------------------------------------------
__global__ void rope_kernel(float* __restrict__ tq,
                            const float* __restrict__ fc,
                            const float* __restrict__ fs, int nh, int total)
{
    int idx = blockIdx.x * blockDim.x + threadIdx.x;
    if (idx >= total) return;
    int p = idx & 63;
    int s = (idx >> 6) / nh % SEQ;
    float c  = fc[s*64 + p];
    float sn = fs[s*64 + p];
    float re = tq[(size_t)idx*2 + 0];
    float im = tq[(size_t)idx*2 + 1];
    tq[(size_t)idx*2 + 0] = re * c  - im * sn;
    tq[(size_t)idx*2 + 1] = re * sn + im * c;
}

// ---------------------------------------------------------------------------
// Causal flash attention, fp32. One CTA = (batch, head, 64-query tile).
// Online softmax; K/V tiles of 64 rows streamed through shared memory.
// ---------------------------------------------------------------------------
#define ATTN_SMEM_FLOATS (3*64*132 + 64*65 + 3*64)

__global__ __launch_bounds__(256) void attn_kernel(
    const float* __restrict__ Q, const float* __restrict__ Kg,
    const float* __restrict__ Vg, float* __restrict__ O)
{
    extern __shared__ float sm[];
    float* Qs = sm;               // 64 x 132
    float* Ks = Qs + 64*132;      // 64 x 132
    float* Vs = Ks + 64*132;      // 64 x 132
    float* Ss = Vs + 64*132;      // 64 x 65
    float* Mr = Ss + 64*65;       // 64
    float* Lr = Mr + 64;          // 64
    float* Ar = Lr + 64;          // 64

    const int t  = threadIdx.x;
    const int qt = blockIdx.x;    // 0..31
    const int h  = blockIdx.y;    // 0..31
    const int b  = blockIdx.z;    // 0..1
    const int hk = h >> 2;        // GQA: 4 q-heads per kv-head
    const int q0 = qt * 64;
    const float scale = 0.08838834764831845f;  // 1/sqrt(128)

    // Load Q tile (pre-scaled)
#pragma unroll
    for (int i = 0; i < 8; i++) {
        int idx = t + i*256;
        int r = idx >> 5, d4 = (idx & 31) * 4;
        float4 vq = *(const float4*)(Q + ((size_t)((b*SEQ + q0 + r)*NH + h))*HD + d4);
        Qs[r*132 + d4 + 0] = vq.x * scale;
        Qs[r*132 + d4 + 1] = vq.y * scale;
        Qs[r*132 + d4 + 2] = vq.z * scale;
        Qs[r*132 + d4 + 3] = vq.w * scale;
    }
    if (t < 64) { Mr[t] = -1e30f; Lr[t] = 0.f; }

    float acc[32];
#pragma unroll
    for (int c = 0; c < 32; c++) acc[c] = 0.f;

    const int txs  = t & 15, tys = t >> 4;   // S-compute layout
    const int rowo = t >> 2, cg  = t & 3;    // O-accum layout: 4 threads/row

    for (int kt = 0; kt <= qt; kt++) {
        __syncthreads();   // Q visible; previous iter's Ks/Vs/Ss consumed
        const int k0 = kt * 64;
#pragma unroll
        for (int i = 0; i < 8; i++) {
            int idx = t + i*256;
            int r = idx >> 5, d4 = (idx & 31) * 4;
            size_t base = ((size_t)((b*SEQ + k0 + r)*NKV + hk))*HD + d4;
            *(float4*)(Ks + r*132 + d4) = *(const float4*)(Kg + base);
            *(float4*)(Vs + r*132 + d4) = *(const float4*)(Vg + base);
        }
        __syncthreads();

        // S = Q K^T : each thread 4 rows (tys*4+i) x 4 cols (txs+16j)
        float sacc[4][4];
#pragma unroll
        for (int i = 0; i < 4; i++)
#pragma unroll
            for (int j = 0; j < 4; j++) sacc[i][j] = 0.f;

        for (int d = 0; d < HD; d++) {
            float qa[4], kb[4];
#pragma unroll
            for (int i = 0; i < 4; i++) qa[i] = Qs[(tys*4 + i)*132 + d];
#pragma unroll
            for (int j = 0; j < 4; j++) kb[j] = Ks[(txs + 16*j)*132 + d];
#pragma unroll
            for (int i = 0; i < 4; i++)
#pragma unroll
                for (int j = 0; j < 4; j++) sacc[i][j] += qa[i] * kb[j];
        }

        const bool diag = (kt == qt);
#pragma unroll
        for (int i = 0; i < 4; i++) {
            int qi = tys*4 + i;
#pragma unroll
            for (int j = 0; j < 4; j++) {
                int kj = txs + 16*j;
                float s = sacc[i][j];
                if (diag && kj > qi) s = -1e30f;   // causal mask
                Ss[qi*65 + kj] = s;
            }
        }
        __syncthreads();

        // Online softmax row pass (one thread per row)
        if (t < 64) {
            int r = t;
            float mold = Mr[r], mx = mold;
            for (int k2 = 0; k2 < 64; k2++) mx = fmaxf(mx, Ss[r*65 + k2]);
            float al = __expf(mold - mx);
            float sum = 0.f;
            for (int k2 = 0; k2 < 64; k2++) {
                float p = __expf(Ss[r*65 + k2] - mx);
                Ss[r*65 + k2] = p;
                sum += p;
            }
            Lr[r] = Lr[r] * al + sum;
            Mr[r] = mx;
            Ar[r] = al;
        }
        __syncthreads();

        // O += P * V  (each thread: one row, cols cg + 4c)
        float al = Ar[rowo];
#pragma unroll
        for (int c = 0; c < 32; c++) acc[c] *= al;
        for (int k2 = 0; k2 < 64; k2++) {
            float p = Ss[rowo*65 + k2];
#pragma unroll
            for (int c = 0; c < 32; c++)
                acc[c] += p * Vs[k2*132 + cg + 4*c];
        }
    }
    __syncthreads();

    float inv = 1.0f / Lr[rowo];
    size_t ob = ((size_t)((b*SEQ + q0 + rowo)*NH + h))*HD + cg;
#pragma unroll
    for (int c = 0; c < 32; c++) O[ob + 4*c] = acc[c] * inv;
}

// ---------------------------------------------------------------------------
extern "C" void kernel_launch(void* const* d_in, const int* in_sizes, int n_in,
                              void* d_out, int out_size)
{
    const float* x    = (const float*)d_in[0];
    // d_in[1] = start_pos (always 0 in this problem)
    const float* fcos = (const float*)d_in[2];
    const float* fsin = (const float*)d_in[3];
    // d_in[4] = mask (pure causal; applied analytically)
    const float* wq   = (const float*)d_in[5];
    const float* wk   = (const float*)d_in[6];
    const float* wv   = (const float*)d_in[7];
    const float* wo   = (const float*)d_in[8];
    // d_in[9], d_in[10] = zero caches, start_pos=0 -> cache == fresh K/V

    float *q, *k, *v, *o;
    cudaGetSymbolAddress((void**)&q, g_q);
    cudaGetSymbolAddress((void**)&k, g_k);
    cudaGetSymbolAddress((void**)&v, g_v);
    cudaGetSymbolAddress((void**)&o, g_o);

    const int M = BSZ * SEQ;  // 4096

    // QKV projections
    sgemm_kernel<<<dim3((NH*HD)/128,  M/128), 256>>>(x, wq, q, M, NH*HD,  DIM);
    sgemm_kernel<<<dim3((NKV*HD)/128, M/128), 256>>>(x, wk, k, M, NKV*HD, DIM);
    sgemm_kernel<<<dim3((NKV*HD)/128, M/128), 256>>>(x, wv, v, M, NKV*HD, DIM);

    // RoPE on q and k
    int qpairs = BSZ*SEQ*NH*(HD/2);
    int kpairs = BSZ*SEQ*NKV*(HD/2);
    rope_kernel<<<(qpairs + 255)/256, 256>>>(q, fcos, fsin, NH,  qpairs);
    rope_kernel<<<(kpairs + 255)/256, 256>>>(k, fcos, fsin, NKV, kpairs);

    // Causal flash attention
    const int smem = ATTN_SMEM_FLOATS * (int)sizeof(float);
    cudaFuncSetAttribute(attn_kernel, cudaFuncAttributeMaxDynamicSharedMemorySize, smem);
    attn_kernel<<<dim3(SEQ/64, NH, BSZ), 256, smem>>>(q, k, v, o);

    // Output projection -> d_out
    sgemm_kernel<<<dim3(DIM/128, M/128), 256>>>(o, wo, (float*)d_out, M, DIM, DIM);
}

// round 7
// speedup vs baseline: 1.9591x; 1.9591x over previous
#include <cuda_runtime.h>
#include <cstdint>
#include <math.h>

#define BSZ 2
#define SEQ 2048
#define DIM 4096
#define NH 32
#define NKV 8
#define HD 128

// Scratch
__device__ float g_q[BSZ*SEQ*NH*HD];    // 64 MB
__device__ float g_k[BSZ*SEQ*NKV*HD];   // 16 MB
__device__ float g_v[BSZ*SEQ*NKV*HD];   // 16 MB
__device__ float g_o[BSZ*SEQ*NH*HD];    // 64 MB (tf32-rounded)
__device__ float g_xc[BSZ*SEQ*DIM];     // 32 MB (x, tf32-rounded)
__device__ float g_wt[41943040];        // 160 MB: wqT | wkT | wvT | woT (tf32-rounded)

// ---------------------------------------------------------------------------
// helpers
// ---------------------------------------------------------------------------
__device__ __forceinline__ float to_tf32(float x) {
    uint32_t r;
    asm("cvt.rna.tf32.f32 %0, %1;" : "=r"(r) : "f"(x));
    return __uint_as_float(r);
}

__device__ __forceinline__ uint32_t smem_u32(const void* p) {
    uint32_t a;
    asm("{ .reg .u64 t; cvta.to.shared.u64 t, %1; cvt.u32.u64 %0, t; }"
        : "=r"(a) : "l"(p));
    return a;
}

__device__ __forceinline__ void cp_async16(uint32_t saddr, const void* gaddr) {
    asm volatile("cp.async.cg.shared.global [%0], [%1], 16;"
                 :: "r"(saddr), "l"(gaddr) : "memory");
}
__device__ __forceinline__ void cp_commit() {
    asm volatile("cp.async.commit_group;" ::: "memory");
}
template <int N>
__device__ __forceinline__ void cp_wait() {
    asm volatile("cp.async.wait_group %0;" :: "n"(N) : "memory");
}

// mma.sync m16n8k8 tf32: D += A*B
__device__ __forceinline__ void mma_tf32(float* c, const uint32_t* a, const uint32_t* b) {
    asm volatile(
        "mma.sync.aligned.m16n8k8.row.col.f32.tf32.tf32.f32 "
        "{%0,%1,%2,%3}, {%4,%5,%6,%7}, {%8,%9}, {%0,%1,%2,%3};"
        : "+f"(c[0]), "+f"(c[1]), "+f"(c[2]), "+f"(c[3])
        : "r"(a[0]), "r"(a[1]), "r"(a[2]), "r"(a[3]), "r"(b[0]), "r"(b[1]));
}

// ---------------------------------------------------------------------------
// Weight transpose + tf32 rounding: in[R][C] -> out[C][R]
// ---------------------------------------------------------------------------
__global__ void transpose_kernel(const float* __restrict__ in,
                                 float* __restrict__ out, int R, int C)
{
    __shared__ float tile[32][33];
    int c0 = blockIdx.x * 32, r0 = blockIdx.y * 32;
    int tx = threadIdx.x, ty = threadIdx.y;
#pragma unroll
    for (int j = 0; j < 32; j += 8)
        tile[ty + j][tx] = in[(size_t)(r0 + ty + j) * C + c0 + tx];
    __syncthreads();
#pragma unroll
    for (int j = 0; j < 32; j += 8)
        out[(size_t)(c0 + ty + j) * R + r0 + tx] = to_tf32(tile[tx][ty + j]);
}

// Elementwise tf32 rounding copy (for x)
__global__ void cvt_copy_kernel(const float* __restrict__ in,
                                float* __restrict__ out, int n4)
{
    int i = blockIdx.x * blockDim.x + threadIdx.x;
    if (i >= n4) return;
    float4 v = ((const float4*)in)[i];
    v.x = to_tf32(v.x); v.y = to_tf32(v.y);
    v.z = to_tf32(v.z); v.w = to_tf32(v.w);
    ((float4*)out)[i] = v;
}

// ---------------------------------------------------------------------------
// tf32 mma.sync GEMM: C[M,N] = A[M,K] * Bt[N,K]^T
// 128x128 tile, BK=32, 256 threads (8 warps, 2x4 grid of 64x32 warp tiles),
// cp.async double buffering, smem stride 36 floats (conflict-free frags).
// ---------------------------------------------------------------------------
#define GS 36                       // smem row stride in floats
#define G_BUF (128*GS)              // 4608 floats per operand tile
#define G_SMEM_FLOATS (4*G_BUF)     // A0 B0 A1 B1
#define G_SMEM_BYTES (G_SMEM_FLOATS*4)   // 73728

__global__ __launch_bounds__(256, 2) void gemm_mma_kernel(
    const float* __restrict__ A, const float* __restrict__ Bt,
    float* __restrict__ C, int M, int N, int K)
{
    extern __shared__ float sm[];
    float* Abuf[2] = { sm,             sm + 2*G_BUF };
    float* Bbuf[2] = { sm + G_BUF,     sm + 3*G_BUF };

    const int t    = threadIdx.x;
    const int lane = t & 31;
    const int warp = t >> 5;
    const int m0   = blockIdx.y * 128, n0 = blockIdx.x * 128;
    const int mb   = (warp & 1) * 64;       // warp M offset
    const int nb   = (warp >> 1) * 32;      // warp N offset
    const int gid  = lane >> 2;             // groupID
    const int tig  = lane & 3;              // thread-in-group

    const uint32_t sA[2] = { smem_u32(Abuf[0]), smem_u32(Abuf[1]) };
    const uint32_t sB[2] = { smem_u32(Bbuf[0]), smem_u32(Bbuf[1]) };

    auto issue_tile = [&](int kt, int buf) {
        const float* Ag = A  + (size_t)m0 * K + kt * 32;
        const float* Bg = Bt + (size_t)n0 * K + kt * 32;
#pragma unroll
        for (int i = 0; i < 4; i++) {
            int id = t + 256 * i;
            int row = id >> 3, c4 = id & 7;
            uint32_t soff = ((uint32_t)row * GS + (uint32_t)c4 * 4) * 4u;
            cp_async16(sA[buf] + soff, Ag + (size_t)row * K + c4 * 4);
            cp_async16(sB[buf] + soff, Bg + (size_t)row * K + c4 * 4);
        }
        cp_commit();
    };

    float acc[4][4][4];
#pragma unroll
    for (int i = 0; i < 4; i++)
#pragma unroll
        for (int j = 0; j < 4; j++)
#pragma unroll
            for (int r = 0; r < 4; r++) acc[i][j][r] = 0.f;

    const int niter = K >> 5;
    issue_tile(0, 0);
    issue_tile(1, 1);
    cp_wait<1>();
    __syncthreads();

    for (int kt = 0; kt < niter; kt++) {
        const int b = kt & 1;
        const float* As = Abuf[b];
        const float* Bs = Bbuf[b];

#pragma unroll
        for (int s = 0; s < 4; s++) {
            const int ks = 8 * s;
            uint32_t af[4][4], bf[4][2];
#pragma unroll
            for (int ma = 0; ma < 4; ma++) {
                int r = mb + ma * 16 + gid;
                af[ma][0] = __float_as_uint(As[r * GS + ks + tig]);
                af[ma][1] = __float_as_uint(As[(r + 8) * GS + ks + tig]);
                af[ma][2] = __float_as_uint(As[r * GS + ks + 4 + tig]);
                af[ma][3] = __float_as_uint(As[(r + 8) * GS + ks + 4 + tig]);
            }
#pragma unroll
            for (int na = 0; na < 4; na++) {
                int n = nb + na * 8 + gid;
                bf[na][0] = __float_as_uint(Bs[n * GS + ks + tig]);
                bf[na][1] = __float_as_uint(Bs[n * GS + ks + 4 + tig]);
            }
#pragma unroll
            for (int ma = 0; ma < 4; ma++)
#pragma unroll
                for (int na = 0; na < 4; na++)
                    mma_tf32(acc[ma][na], af[ma], bf[na]);
        }

        if (kt + 1 < niter) {
            __syncthreads();                 // all readers of buf b done
            if (kt + 2 < niter) { issue_tile(kt + 2, b); cp_wait<1>(); }
            else                { cp_wait<0>(); }
            __syncthreads();                 // tile kt+1 visible
        }
    }

    // epilogue: direct float2 stores
#pragma unroll
    for (int ma = 0; ma < 4; ma++) {
#pragma unroll
        for (int na = 0; na < 4; na++) {
            int row = m0 + mb + ma * 16 + gid;
            int col = n0 + nb + na * 8 + 2 * tig;
            float2 v0 = make_float2(acc[ma][na][0], acc[ma][na][1]);
            float2 v1 = make_float2(acc[ma][na][2], acc[ma][na][3]);
            *(float2*)(C + (size_t)row * N + col) = v0;
            *(float2*)(C + (size_t)(row + 8) * N + col) = v1;
        }
    }
}

// ---------------------------------------------------------------------------
// RoPE (in place)
// ---------------------------------------------------------------------------
__global__ void rope_kernel(float* __restrict__ tq,
                            const float* __restrict__ fc,
                            const float* __restrict__ fs, int nh, int total)
{
    int idx = blockIdx.x * blockDim.x + threadIdx.x;
    if (idx >= total) return;
    int p = idx & 63;
    int s = (idx >> 6) / nh % SEQ;
    float c  = fc[s*64 + p];
    float sn = fs[s*64 + p];
    float re = tq[(size_t)idx*2 + 0];
    float im = tq[(size_t)idx*2 + 1];
    tq[(size_t)idx*2 + 0] = re * c  - im * sn;
    tq[(size_t)idx*2 + 1] = re * sn + im * c;
}

// ---------------------------------------------------------------------------
// Causal flash attention, fp32 SIMT. Output rounded to tf32 (feeds wo GEMM).
// ---------------------------------------------------------------------------
#define ATTN_SMEM_FLOATS (3*64*132 + 64*65 + 3*64)

__global__ __launch_bounds__(256) void attn_kernel(
    const float* __restrict__ Q, const float* __restrict__ Kg,
    const float* __restrict__ Vg, float* __restrict__ O)
{
    extern __shared__ float sm[];
    float* Qs = sm;
    float* Ks = Qs + 64*132;
    float* Vs = Ks + 64*132;
    float* Ss = Vs + 64*132;
    float* Mr = Ss + 64*65;
    float* Lr = Mr + 64;
    float* Ar = Lr + 64;

    const int t  = threadIdx.x;
    const int qt = blockIdx.x;
    const int h  = blockIdx.y;
    const int b  = blockIdx.z;
    const int hk = h >> 2;
    const int q0 = qt * 64;
    const float scale = 0.08838834764831845f;

#pragma unroll
    for (int i = 0; i < 8; i++) {
        int idx = t + i*256;
        int r = idx >> 5, d4 = (idx & 31) * 4;
        float4 vq = *(const float4*)(Q + ((size_t)((b*SEQ + q0 + r)*NH + h))*HD + d4);
        Qs[r*132 + d4 + 0] = vq.x * scale;
        Qs[r*132 + d4 + 1] = vq.y * scale;
        Qs[r*132 + d4 + 2] = vq.z * scale;
        Qs[r*132 + d4 + 3] = vq.w * scale;
    }
    if (t < 64) { Mr[t] = -1e30f; Lr[t] = 0.f; }

    float acc[32];
#pragma unroll
    for (int c = 0; c < 32; c++) acc[c] = 0.f;

    const int txs  = t & 15, tys = t >> 4;
    const int rowo = t >> 2, cg  = t & 3;

    for (int kt = 0; kt <= qt; kt++) {
        __syncthreads();
        const int k0 = kt * 64;
#pragma unroll
        for (int i = 0; i < 8; i++) {
            int idx = t + i*256;
            int r = idx >> 5, d4 = (idx & 31) * 4;
            size_t base = ((size_t)((b*SEQ + k0 + r)*NKV + hk))*HD + d4;
            *(float4*)(Ks + r*132 + d4) = *(const float4*)(Kg + base);
            *(float4*)(Vs + r*132 + d4) = *(const float4*)(Vg + base);
        }
        __syncthreads();

        float sacc[4][4];
#pragma unroll
        for (int i = 0; i < 4; i++)
#pragma unroll
            for (int j = 0; j < 4; j++) sacc[i][j] = 0.f;

        for (int d = 0; d < HD; d++) {
            float qa[4], kb[4];
#pragma unroll
            for (int i = 0; i < 4; i++) qa[i] = Qs[(tys*4 + i)*132 + d];
#pragma unroll
            for (int j = 0; j < 4; j++) kb[j] = Ks[(txs + 16*j)*132 + d];
#pragma unroll
            for (int i = 0; i < 4; i++)
#pragma unroll
                for (int j = 0; j < 4; j++) sacc[i][j] += qa[i] * kb[j];
        }

        const bool diag = (kt == qt);
#pragma unroll
        for (int i = 0; i < 4; i++) {
            int qi = tys*4 + i;
#pragma unroll
            for (int j = 0; j < 4; j++) {
                int kj = txs + 16*j;
                float s = sacc[i][j];
                if (diag && kj > qi) s = -1e30f;
                Ss[qi*65 + kj] = s;
            }
        }
        __syncthreads();

        if (t < 64) {
            int r = t;
            float mold = Mr[r], mx = mold;
            for (int k2 = 0; k2 < 64; k2++) mx = fmaxf(mx, Ss[r*65 + k2]);
            float al = __expf(mold - mx);
            float sum = 0.f;
            for (int k2 = 0; k2 < 64; k2++) {
                float p = __expf(Ss[r*65 + k2] - mx);
                Ss[r*65 + k2] = p;
                sum += p;
            }
            Lr[r] = Lr[r] * al + sum;
            Mr[r] = mx;
            Ar[r] = al;
        }
        __syncthreads();

        float al = Ar[rowo];
#pragma unroll
        for (int c = 0; c < 32; c++) acc[c] *= al;
        for (int k2 = 0; k2 < 64; k2++) {
            float p = Ss[rowo*65 + k2];
#pragma unroll
            for (int c = 0; c < 32; c++)
                acc[c] += p * Vs[k2*132 + cg + 4*c];
        }
    }
    __syncthreads();

    float inv = 1.0f / Lr[rowo];
    size_t ob = ((size_t)((b*SEQ + q0 + rowo)*NH + h))*HD + cg;
#pragma unroll
    for (int c = 0; c < 32; c++) O[ob + 4*c] = to_tf32(acc[c] * inv);
}

// ---------------------------------------------------------------------------
extern "C" void kernel_launch(void* const* d_in, const int* in_sizes, int n_in,
                              void* d_out, int out_size)
{
    const float* x    = (const float*)d_in[0];
    const float* fcos = (const float*)d_in[2];
    const float* fsin = (const float*)d_in[3];
    const float* wq   = (const float*)d_in[5];
    const float* wk   = (const float*)d_in[6];
    const float* wv   = (const float*)d_in[7];
    const float* wo   = (const float*)d_in[8];

    float *q, *k, *v, *o, *xc, *wt;
    cudaGetSymbolAddress((void**)&q,  g_q);
    cudaGetSymbolAddress((void**)&k,  g_k);
    cudaGetSymbolAddress((void**)&v,  g_v);
    cudaGetSymbolAddress((void**)&o,  g_o);
    cudaGetSymbolAddress((void**)&xc, g_xc);
    cudaGetSymbolAddress((void**)&wt, g_wt);

    float* wqT = wt;                 // [4096][4096]
    float* wkT = wt + 16777216;      // [1024][4096]
    float* wvT = wt + 20971520;      // [1024][4096]
    float* woT = wt + 25165824;      // [4096][4096]

    const int M = BSZ * SEQ;  // 4096

    // tf32-round all GEMM inputs once
    int xn4 = (BSZ*SEQ*DIM) / 4;
    cvt_copy_kernel<<<(xn4 + 255)/256, 256>>>(x, xc, xn4);

    dim3 tb(32, 8);
    transpose_kernel<<<dim3(DIM/32, DIM/32), tb>>>(wq, wqT, DIM, DIM);
    transpose_kernel<<<dim3((NKV*HD)/32, DIM/32), tb>>>(wk, wkT, DIM, NKV*HD);
    transpose_kernel<<<dim3((NKV*HD)/32, DIM/32), tb>>>(wv, wvT, DIM, NKV*HD);
    transpose_kernel<<<dim3(DIM/32, DIM/32), tb>>>(wo, woT, NH*HD, DIM);

    cudaFuncSetAttribute(gemm_mma_kernel,
                         cudaFuncAttributeMaxDynamicSharedMemorySize, G_SMEM_BYTES);

    gemm_mma_kernel<<<dim3((NH*HD)/128,  M/128), 256, G_SMEM_BYTES>>>(xc, wqT, q, M, NH*HD,  DIM);
    gemm_mma_kernel<<<dim3((NKV*HD)/128, M/128), 256, G_SMEM_BYTES>>>(xc, wkT, k, M, NKV*HD, DIM);
    gemm_mma_kernel<<<dim3((NKV*HD)/128, M/128), 256, G_SMEM_BYTES>>>(xc, wvT, v, M, NKV*HD, DIM);

    int qpairs = BSZ*SEQ*NH*(HD/2);
    int kpairs = BSZ*SEQ*NKV*(HD/2);
    rope_kernel<<<(qpairs + 255)/256, 256>>>(q, fcos, fsin, NH,  qpairs);
    rope_kernel<<<(kpairs + 255)/256, 256>>>(k, fcos, fsin, NKV, kpairs);

    const int smem = ATTN_SMEM_FLOATS * (int)sizeof(float);
    cudaFuncSetAttribute(attn_kernel, cudaFuncAttributeMaxDynamicSharedMemorySize, smem);
    attn_kernel<<<dim3(SEQ/64, NH, BSZ), 256, smem>>>(q, k, v, o);

    gemm_mma_kernel<<<dim3(DIM/128, M/128), 256, G_SMEM_BYTES>>>(o, woT, (float*)d_out, M, DIM, DIM);
}